// round 1
// baseline (speedup 1.0000x reference)
#include <cuda_runtime.h>

// ---------------- scratch (no allocations allowed) ----------------
__device__ float g_Wt[512 * 4096];     // [(n*64+k)][(i*64+j)]   8 MB
__device__ float g_bsum[256 * 64];     // [q][j]
__device__ float g_A2[2048 * 64];      // [(n*256+p)][i]
__device__ float g_S1[256 * 4096];     // [r][(i*64+j)]          4 MB
__device__ float g_S2[16384 * 256];    // [(r*64+i)][q]         16 MB
__device__ float g_M2[64 * 65536];     // [i][(q*256+r)]        16 MB

// ---------------- prep kernels ----------------
__global__ void k_bsum(const float* __restrict__ b) {
    int idx = blockIdx.x * blockDim.x + threadIdx.x;   // 16384
    int q = idx >> 6, j = idx & 63;
    float s = 0.f;
#pragma unroll
    for (int n = 0; n < 8; n++) s += b[q * 512 + n * 64 + j];
    g_bsum[idx] = s;
}

__global__ void k_a2(const float* __restrict__ a) {
    int idx = blockIdx.x * blockDim.x + threadIdx.x;   // 131072
    int np = idx >> 6, i = idx & 63;
    int n = np >> 8, p = np & 255;
    g_A2[idx] = a[p * 512 + n * 64 + i];
}

// W[n][i][j][k] -> Wt[(n*64+k)][(i*64+j)]
__global__ void k_wt(const float* __restrict__ W) {
    __shared__ float sm[64][65];
    int ni = blockIdx.x;                   // n*64+i
    int n = ni >> 6, i = ni & 63;
    const float* Wni = W + ((size_t)n * 262144 + (size_t)i * 4096);
    for (int t = threadIdx.x; t < 4096; t += blockDim.x) {
        int j = t >> 6, k = t & 63;
        sm[j][k] = Wni[t];                 // coalesced in k
    }
    __syncthreads();
    for (int t = threadIdx.x; t < 4096; t += blockDim.x) {
        int k = t >> 6, j = t & 63;
        g_Wt[(size_t)(n * 64 + k) * 4096 + i * 64 + j] = sm[j][k];  // coalesced in j
    }
}

// ---------------- GEMM1: S1[256x4096] = c[256x512] @ Wt[512x4096] ----------------
__global__ void __launch_bounds__(256) k_gemm1(const float* __restrict__ A) {
    __shared__ float As[32][65];   // [k][m]
    __shared__ float Bs[32][64];   // [k][n]
    int m0 = blockIdx.y * 64;
    int n0 = blockIdx.x * 64;
    int tid = threadIdx.x;
    int tx = tid & 15, ty = tid >> 4;
    float acc[4][4] = {};
    for (int k0 = 0; k0 < 512; k0 += 32) {
        for (int t = tid; t < 2048; t += 256) {
            int m = t >> 5, k = t & 31;
            As[k][m] = A[(m0 + m) * 512 + k0 + k];
        }
        for (int t = tid; t < 2048; t += 256) {
            int k = t >> 6, n = t & 63;
            Bs[k][n] = g_Wt[(size_t)(k0 + k) * 4096 + n0 + n];
        }
        __syncthreads();
#pragma unroll 8
        for (int k = 0; k < 32; k++) {
            float av[4], bv[4];
#pragma unroll
            for (int u = 0; u < 4; u++) av[u] = As[k][ty * 4 + u];
#pragma unroll
            for (int v = 0; v < 4; v++) bv[v] = Bs[k][tx * 4 + v];
#pragma unroll
            for (int u = 0; u < 4; u++)
#pragma unroll
                for (int v = 0; v < 4; v++) acc[u][v] += av[u] * bv[v];
        }
        __syncthreads();
    }
#pragma unroll
    for (int u = 0; u < 4; u++)
#pragma unroll
        for (int v = 0; v < 4; v++)
            g_S1[(size_t)(m0 + ty * 4 + u) * 4096 + n0 + tx * 4 + v] = acc[u][v];
}

// ---------------- GEMM2: S2[16384x256] = S1(view 16384x64) @ bsum^T ----------------
__global__ void __launch_bounds__(256) k_gemm2() {
    __shared__ float As[64][65];   // [m][j]
    __shared__ float Bs[64][65];   // [j][q]
    int m0 = blockIdx.y * 64;
    int n0 = blockIdx.x * 64;
    int tid = threadIdx.x;
    int tx = tid & 15, ty = tid >> 4;
    for (int t = tid; t < 4096; t += 256) {
        int m = t >> 6, j = t & 63;
        As[m][j] = g_S1[(size_t)(m0 + m) * 64 + j];
    }
    for (int t = tid; t < 4096; t += 256) {
        int q = t >> 6, j = t & 63;
        Bs[j][q] = g_bsum[(n0 + q) * 64 + j];
    }
    __syncthreads();
    float acc[4][4] = {};
#pragma unroll 8
    for (int j = 0; j < 64; j++) {
        float av[4], bv[4];
#pragma unroll
        for (int u = 0; u < 4; u++) av[u] = As[ty * 4 + u][j];
#pragma unroll
        for (int v = 0; v < 4; v++) bv[v] = Bs[j][tx * 4 + v];
#pragma unroll
        for (int u = 0; u < 4; u++)
#pragma unroll
            for (int v = 0; v < 4; v++) acc[u][v] += av[u] * bv[v];
    }
#pragma unroll
    for (int u = 0; u < 4; u++)
#pragma unroll
        for (int v = 0; v < 4; v++)
            g_S2[(size_t)(m0 + ty * 4 + u) * 256 + n0 + tx * 4 + v] = acc[u][v];
}

// ---------------- transpose S2[(r*64+i)][q] -> M2[i][(q*256+r)] ----------------
__global__ void k_t2() {
    __shared__ float sm[32][33];
    int i = blockIdx.z;           // 0..63
    int rt = blockIdx.y;          // 0..7
    int qt = blockIdx.x;          // 0..7
    int tx = threadIdx.x, ty = threadIdx.y;   // 32 x 8
    for (int yy = ty; yy < 32; yy += 8) {
        int r = rt * 32 + yy, q = qt * 32 + tx;
        sm[yy][tx] = g_S2[(size_t)(r * 64 + i) * 256 + q];   // coalesced in q
    }
    __syncthreads();
    for (int yy = ty; yy < 32; yy += 8) {
        int q = qt * 32 + yy, r = rt * 32 + tx;
        g_M2[(size_t)i * 65536 + q * 256 + r] = sm[tx][yy];  // coalesced in r
    }
}

// ---------------- GEMM3: out[2048x65536] = A2[2048x64] @ M2[64x65536] ----------------
// block tile 64 rows x 128 cols (2 q x 64 r), 256 threads, 8x4 micro-tile
__global__ void __launch_bounds__(256) k_gemm3(float* __restrict__ out) {
    __shared__ float As[64][64];    // [np_local][i]   16 KB
    __shared__ float Bs[64][128];   // [i][c]          32 KB
    int np0 = blockIdx.y * 64;
    int qt = blockIdx.x >> 2;       // 0..127 -> q0 = qt*2
    int rt = blockIdx.x & 3;        // r0 = rt*64
    int q0 = qt * 2, r0 = rt * 64;
    int tid = threadIdx.x;

    // load A tile (float4, coalesced)
    for (int t = tid; t < 1024; t += 256) {
        int m = t >> 4, k4 = t & 15;
        *(float4*)&As[m][k4 * 4] =
            *(const float4*)&g_A2[(size_t)(np0 + m) * 64 + k4 * 4];
    }
    // load B tile (float4, coalesced: r is contiguous in M2)
    for (int t = tid; t < 2048; t += 256) {
        int k = t >> 5, c = (t & 31) * 4;
        int ql = c >> 6, rl = c & 63;
        *(float4*)&Bs[k][c] =
            *(const float4*)&g_M2[(size_t)k * 65536 + (size_t)(q0 + ql) * 256 + r0 + rl];
    }
    __syncthreads();

    int tx = tid & 31, ty = tid >> 5;
    float acc[8][4] = {};
#pragma unroll 8
    for (int k = 0; k < 64; k++) {
        float av[8];
#pragma unroll
        for (int u = 0; u < 8; u++) av[u] = As[ty * 8 + u][k];   // warp-broadcast
        float4 b4 = *(float4*)&Bs[k][tx * 4];
        float bv[4] = {b4.x, b4.y, b4.z, b4.w};
#pragma unroll
        for (int u = 0; u < 8; u++)
#pragma unroll
            for (int v = 0; v < 4; v++) acc[u][v] += av[u] * bv[v];
    }

    int c = tx * 4;
    int q = q0 + (c >> 6), r = r0 + (c & 63);
    size_t colbase = (size_t)q * 256 + r;
#pragma unroll
    for (int u = 0; u < 8; u++) {
        size_t np = np0 + ty * 8 + u;
        float4 o = make_float4(acc[u][0], acc[u][1], acc[u][2], acc[u][3]);
        *(float4*)&out[np * 65536 + colbase] = o;   // STG.128, fully coalesced
    }
}

// ---------------- launch ----------------
extern "C" void kernel_launch(void* const* d_in, const int* in_sizes, int n_in,
                              void* d_out, int out_size) {
    const float* c = (const float*)d_in[0];   // [1,256,8,64]
    const float* b = (const float*)d_in[1];   // [1,256,8,64]
    const float* a = (const float*)d_in[2];   // [1,256,8,64]
    const float* W = (const float*)d_in[3];   // [8,64,64,64]
    float* out = (float*)d_out;               // [1,8,256,256,256]

    k_bsum<<<64, 256>>>(b);
    k_a2<<<512, 256>>>(a);
    k_wt<<<512, 256>>>(W);
    k_gemm1<<<dim3(64, 4), 256>>>(c);
    k_gemm2<<<dim3(4, 256), 256>>>();
    k_t2<<<dim3(8, 8, 64), dim3(32, 8)>>>();
    k_gemm3<<<dim3(512, 32), 256>>>(out);
}

// round 3
// speedup vs baseline: 1.7339x; 1.7339x over previous
#include <cuda_runtime.h>
#include <cuda_bf16.h>
#include <cstdint>

// ---------------- scratch (no allocations allowed) ----------------
__device__ float g_Wt[512 * 4096];          // [(n*64+k)][(i*64+j)]   8 MB
__device__ float g_bsum[256 * 64];          // [q][j]
__device__ float g_S1[256 * 4096];          // [r][(i*64+j)]          4 MB
__device__ float g_S2[16384 * 256];         // [(r*64+i)][q]         16 MB
__device__ __nv_bfloat16 g_A2h[2048 * 64];  // [(n*256+p)][i] hi
__device__ __nv_bfloat16 g_A2l[2048 * 64];  // lo
__device__ __nv_bfloat16 g_B3h[65536 * 64]; // [(q*256+r)][i] hi      8 MB
__device__ __nv_bfloat16 g_B3l[65536 * 64]; // lo                     8 MB

__device__ __forceinline__ void bf16_split(float x, __nv_bfloat16& h, __nv_bfloat16& l) {
    h = __float2bfloat16(x);
    l = __float2bfloat16(x - __bfloat162float(h));
}

// ---------------- prep kernels ----------------
__global__ void k_bsum(const float* __restrict__ b) {
    int idx = blockIdx.x * blockDim.x + threadIdx.x;   // 16384
    int q = idx >> 6, j = idx & 63;
    float s = 0.f;
#pragma unroll
    for (int n = 0; n < 8; n++) s += b[q * 512 + n * 64 + j];
    g_bsum[idx] = s;
}

__global__ void k_a2(const float* __restrict__ a) {
    int idx = blockIdx.x * blockDim.x + threadIdx.x;   // 131072
    int np = idx >> 6, i = idx & 63;
    int n = np >> 8, p = np & 255;
    __nv_bfloat16 h, l;
    bf16_split(a[p * 512 + n * 64 + i], h, l);
    g_A2h[idx] = h;
    g_A2l[idx] = l;
}

// W[n][i][j][k] -> Wt[(n*64+k)][(i*64+j)]
__global__ void k_wt(const float* __restrict__ W) {
    __shared__ float sm[64][65];
    int ni = blockIdx.x;
    int n = ni >> 6, i = ni & 63;
    const float* Wni = W + ((size_t)n * 262144 + (size_t)i * 4096);
    for (int t = threadIdx.x; t < 4096; t += blockDim.x) {
        int j = t >> 6, k = t & 63;
        sm[j][k] = Wni[t];
    }
    __syncthreads();
    for (int t = threadIdx.x; t < 4096; t += blockDim.x) {
        int k = t >> 6, j = t & 63;
        g_Wt[(size_t)(n * 64 + k) * 4096 + i * 64 + j] = sm[j][k];
    }
}

// ---------------- GEMM1: S1[256x4096] = c[256x512] @ Wt[512x4096] ----------------
__global__ void __launch_bounds__(256) k_gemm1(const float* __restrict__ A) {
    __shared__ float As[32][65];
    __shared__ float Bs[32][64];
    int m0 = blockIdx.y * 64;
    int n0 = blockIdx.x * 64;
    int tid = threadIdx.x;
    int tx = tid & 15, ty = tid >> 4;
    float acc[4][4] = {};
    for (int k0 = 0; k0 < 512; k0 += 32) {
        for (int t = tid; t < 2048; t += 256) {
            int m = t >> 5, k = t & 31;
            As[k][m] = A[(m0 + m) * 512 + k0 + k];
        }
        for (int t = tid; t < 2048; t += 256) {
            int k = t >> 6, n = t & 63;
            Bs[k][n] = g_Wt[(size_t)(k0 + k) * 4096 + n0 + n];
        }
        __syncthreads();
#pragma unroll 8
        for (int k = 0; k < 32; k++) {
            float av[4], bv[4];
#pragma unroll
            for (int u = 0; u < 4; u++) av[u] = As[k][ty * 4 + u];
#pragma unroll
            for (int v = 0; v < 4; v++) bv[v] = Bs[k][tx * 4 + v];
#pragma unroll
            for (int u = 0; u < 4; u++)
#pragma unroll
                for (int v = 0; v < 4; v++) acc[u][v] += av[u] * bv[v];
        }
        __syncthreads();
    }
#pragma unroll
    for (int u = 0; u < 4; u++)
#pragma unroll
        for (int v = 0; v < 4; v++)
            g_S1[(size_t)(m0 + ty * 4 + u) * 4096 + n0 + tx * 4 + v] = acc[u][v];
}

// ---------------- GEMM2: S2[16384x256] = S1(view 16384x64) @ bsum^T ----------------
__global__ void __launch_bounds__(256) k_gemm2() {
    __shared__ float As[64][65];
    __shared__ float Bs[64][65];
    int m0 = blockIdx.y * 64;
    int n0 = blockIdx.x * 64;
    int tid = threadIdx.x;
    int tx = tid & 15, ty = tid >> 4;
    for (int t = tid; t < 4096; t += 256) {
        int m = t >> 6, j = t & 63;
        As[m][j] = g_S1[(size_t)(m0 + m) * 64 + j];
    }
    for (int t = tid; t < 4096; t += 256) {
        int q = t >> 6, j = t & 63;
        Bs[j][q] = g_bsum[(n0 + q) * 64 + j];
    }
    __syncthreads();
    float acc[4][4] = {};
#pragma unroll 8
    for (int j = 0; j < 64; j++) {
        float av[4], bv[4];
#pragma unroll
        for (int u = 0; u < 4; u++) av[u] = As[ty * 4 + u][j];
#pragma unroll
        for (int v = 0; v < 4; v++) bv[v] = Bs[j][tx * 4 + v];
#pragma unroll
        for (int u = 0; u < 4; u++)
#pragma unroll
            for (int v = 0; v < 4; v++) acc[u][v] += av[u] * bv[v];
    }
#pragma unroll
    for (int u = 0; u < 4; u++)
#pragma unroll
        for (int v = 0; v < 4; v++)
            g_S2[(size_t)(m0 + ty * 4 + u) * 256 + n0 + tx * 4 + v] = acc[u][v];
}

// ---------------- transpose+split: S2[(r*64+i)][q] -> B3[(q*256+r)][i] bf16 hi/lo ----
__global__ void k_t2() {
    __shared__ float sm[32][33];
    int mt = blockIdx.x;          // 0..511
    int qt = blockIdx.y;          // 0..7
    int tx = threadIdx.x, ty = threadIdx.y;   // 32 x 8
    for (int yy = ty; yy < 32; yy += 8)
        sm[yy][tx] = g_S2[(size_t)(mt * 32 + yy) * 256 + qt * 32 + tx];
    __syncthreads();
    for (int yy = ty; yy < 32; yy += 8) {
        int q = qt * 32 + yy, m = mt * 32 + tx;
        __nv_bfloat16 h, l;
        bf16_split(sm[tx][yy], h, l);
        g_B3h[(size_t)q * 16384 + m] = h;
        g_B3l[(size_t)q * 16384 + m] = l;
    }
}

// ---------------- GEMM3 (HMMA): out[2048x65536] = A2 @ B3^T, K=64 ----------------
// mma.sync.m16n8k16 bf16, 3-term error-compensated (Ah*Bh + Ah*Bl + Al*Bh)

__device__ __forceinline__ void mma16816(float* c, const uint32_t* a, const uint32_t* b) {
    asm volatile(
        "mma.sync.aligned.m16n8k16.row.col.f32.bf16.bf16.f32 "
        "{%0,%1,%2,%3}, {%4,%5,%6,%7}, {%8,%9}, {%0,%1,%2,%3};"
        : "+f"(c[0]), "+f"(c[1]), "+f"(c[2]), "+f"(c[3])
        : "r"(a[0]), "r"(a[1]), "r"(a[2]), "r"(a[3]), "r"(b[0]), "r"(b[1]));
}

static constexpr int LDT = 72;                 // padded smem stride (bf16 elems)
static constexpr int TILE_E = 128 * LDT;       // elems per tile
static constexpr int SM3_BYTES = 4 * TILE_E * 2;   // 73728 B

__global__ void __launch_bounds__(256) k_gemm3(float* __restrict__ out) {
    extern __shared__ __nv_bfloat16 sm3[];
    __nv_bfloat16* Ah = sm3;
    __nv_bfloat16* Al = Ah + TILE_E;
    __nv_bfloat16* Bh = Al + TILE_E;
    __nv_bfloat16* Bl = Bh + TILE_E;

    int tid = threadIdx.x;
    int wid = tid >> 5, lane = tid & 31;
    int g = lane >> 2, tg = lane & 3;

    int c0 = blockIdx.x * 128;   // column tile (q*256+r)
    size_t m0 = blockIdx.y * 128;   // row tile (n*256+p)

    // stage 4 tiles: 128 rows x 64 bf16 each (8 x uint4 per row)
    {
        const uint4* sA_h = (const uint4*)(g_A2h + m0 * 64);
        const uint4* sA_l = (const uint4*)(g_A2l + m0 * 64);
        const uint4* sB_h = (const uint4*)(g_B3h + (size_t)c0 * 64);
        const uint4* sB_l = (const uint4*)(g_B3l + (size_t)c0 * 64);
        for (int t = tid; t < 1024; t += 256) {
            int row = t >> 3, c = t & 7;
            int d = row * LDT + c * 8;
            *(uint4*)(Ah + d) = sA_h[t];
            *(uint4*)(Al + d) = sA_l[t];
            *(uint4*)(Bh + d) = sB_h[t];
            *(uint4*)(Bl + d) = sB_l[t];
        }
    }
    __syncthreads();

    int wm = (wid >> 2) * 64;    // warp m offset (0 or 64)
    int wn = (wid & 3) * 32;     // warp n offset

    float acc[4][4][4] = {};

#pragma unroll
    for (int ks = 0; ks < 4; ks++) {
        int kc = ks * 16 + tg * 2;
        // B fragments (hi and lo)
        uint32_t fbh[4][2], fbl[4][2];
#pragma unroll
        for (int nt = 0; nt < 4; nt++) {
            int n = (wn + nt * 8 + g) * LDT + kc;
            fbh[nt][0] = *(const uint32_t*)(Bh + n);
            fbh[nt][1] = *(const uint32_t*)(Bh + n + 8);
            fbl[nt][0] = *(const uint32_t*)(Bl + n);
            fbl[nt][1] = *(const uint32_t*)(Bl + n + 8);
        }
        // A-hi fragments; do Ah*Bh and Ah*Bl
        uint32_t fa[4][4];
#pragma unroll
        for (int mt = 0; mt < 4; mt++) {
            int r0 = (wm + mt * 16 + g) * LDT + kc;
            int r1 = r0 + 8 * LDT;
            fa[mt][0] = *(const uint32_t*)(Ah + r0);
            fa[mt][1] = *(const uint32_t*)(Ah + r1);
            fa[mt][2] = *(const uint32_t*)(Ah + r0 + 8);
            fa[mt][3] = *(const uint32_t*)(Ah + r1 + 8);
        }
#pragma unroll
        for (int mt = 0; mt < 4; mt++)
#pragma unroll
            for (int nt = 0; nt < 4; nt++) {
                mma16816(acc[mt][nt], fa[mt], fbh[nt]);
                mma16816(acc[mt][nt], fa[mt], fbl[nt]);
            }
        // A-lo fragments; do Al*Bh
#pragma unroll
        for (int mt = 0; mt < 4; mt++) {
            int r0 = (wm + mt * 16 + g) * LDT + kc;
            int r1 = r0 + 8 * LDT;
            fa[mt][0] = *(const uint32_t*)(Al + r0);
            fa[mt][1] = *(const uint32_t*)(Al + r1);
            fa[mt][2] = *(const uint32_t*)(Al + r0 + 8);
            fa[mt][3] = *(const uint32_t*)(Al + r1 + 8);
        }
#pragma unroll
        for (int mt = 0; mt < 4; mt++)
#pragma unroll
            for (int nt = 0; nt < 4; nt++)
                mma16816(acc[mt][nt], fa[mt], fbh[nt]);
    }

    // epilogue: c0,c1 at (row, col..col+1); c2,c3 at (row+8, ...)
#pragma unroll
    for (int mt = 0; mt < 4; mt++) {
        size_t row = m0 + wm + mt * 16 + g;
        float* o0 = out + row * 65536;
        float* o1 = o0 + 8 * 65536;
#pragma unroll
        for (int nt = 0; nt < 4; nt++) {
            int col = c0 + wn + nt * 8 + tg * 2;
            *(float2*)(o0 + col) = make_float2(acc[mt][nt][0], acc[mt][nt][1]);
            *(float2*)(o1 + col) = make_float2(acc[mt][nt][2], acc[mt][nt][3]);
        }
    }
}

// ---------------- launch ----------------
extern "C" void kernel_launch(void* const* d_in, const int* in_sizes, int n_in,
                              void* d_out, int out_size) {
    const float* c = (const float*)d_in[0];   // [1,256,8,64]
    const float* b = (const float*)d_in[1];   // [1,256,8,64]
    const float* a = (const float*)d_in[2];   // [1,256,8,64]
    const float* W = (const float*)d_in[3];   // [8,64,64,64]
    float* out = (float*)d_out;               // [1,8,256,256,256]

    cudaFuncSetAttribute(k_gemm3, cudaFuncAttributeMaxDynamicSharedMemorySize, SM3_BYTES);

    k_bsum<<<64, 256>>>(b);
    k_a2<<<512, 256>>>(a);
    k_wt<<<512, 256>>>(W);
    k_gemm1<<<dim3(64, 4), 256>>>(c);
    k_gemm2<<<dim3(4, 256), 256>>>();
    k_t2<<<dim3(512, 8), dim3(32, 8)>>>();
    k_gemm3<<<dim3(512, 16), 256, SM3_BYTES>>>(out);
}

// round 4
// speedup vs baseline: 2.1021x; 1.2124x over previous
#include <cuda_runtime.h>
#include <cuda_bf16.h>
#include <cstdint>

// ---------------- scratch (no allocations allowed) ----------------
__device__ __nv_bfloat16 g_Ch[256 * 512];    // c split  [r][(n*64+k)]
__device__ __nv_bfloat16 g_Cl[256 * 512];
__device__ __nv_bfloat16 g_Wtbh[4096 * 512]; // W remap  [(i*64+j)][(n*64+k)]  4 MB
__device__ __nv_bfloat16 g_Wtbl[4096 * 512];
__device__ __nv_bfloat16 g_bsumh[256 * 64];  // [q][j]
__device__ __nv_bfloat16 g_bsuml[256 * 64];
__device__ __nv_bfloat16 g_S1h[16384 * 64];  // [(r*64+i)][j]   2 MB
__device__ __nv_bfloat16 g_S1l[16384 * 64];
__device__ __nv_bfloat16 g_A2h[2048 * 64];   // [(n*256+p)][i]
__device__ __nv_bfloat16 g_A2l[2048 * 64];
__device__ __nv_bfloat16 g_B3h[65536 * 64];  // [(q*256+r)][i]  8 MB
__device__ __nv_bfloat16 g_B3l[65536 * 64];

__device__ __forceinline__ void bf16_split(float x, __nv_bfloat16& h, __nv_bfloat16& l) {
    h = __float2bfloat16(x);
    l = __float2bfloat16(x - __bfloat162float(h));
}
__device__ __forceinline__ uint32_t pack2(__nv_bfloat16 a, __nv_bfloat16 b) {
    __nv_bfloat162 t;
    t.x = a; t.y = b;
    return *(uint32_t*)&t;
}

// ---------------- prep kernels ----------------
__global__ void k_bsum(const float* __restrict__ b) {
    int idx = blockIdx.x * blockDim.x + threadIdx.x;   // 16384
    int q = idx >> 6, j = idx & 63;
    float s = 0.f;
#pragma unroll
    for (int n = 0; n < 8; n++) s += b[q * 512 + n * 64 + j];
    __nv_bfloat16 h, l;
    bf16_split(s, h, l);
    g_bsumh[idx] = h;
    g_bsuml[idx] = l;
}

__global__ void k_csplit(const float* __restrict__ c) {
    int idx = blockIdx.x * blockDim.x + threadIdx.x;   // 131072
    __nv_bfloat16 h, l;
    bf16_split(c[idx], h, l);
    g_Ch[idx] = h;
    g_Cl[idx] = l;
}

__global__ void k_a2(const float* __restrict__ a) {
    int idx = blockIdx.x * blockDim.x + threadIdx.x;   // 131072
    int np = idx >> 6, i = idx & 63;
    int n = np >> 8, p = np & 255;
    __nv_bfloat16 h, l;
    bf16_split(a[p * 512 + n * 64 + i], h, l);
    g_A2h[idx] = h;
    g_A2l[idx] = l;
}

// W[n][i][j][k] -> Wtb[(i*64+j)][(n*64+k)]  (k stays contiguous: pure row remap)
__global__ void k_wt(const float* __restrict__ W) {
    int idx = blockIdx.x * blockDim.x + threadIdx.x;   // 2097152
    int n = idx >> 18, i = (idx >> 12) & 63, j = (idx >> 6) & 63, k = idx & 63;
    size_t dst = (size_t)(i * 64 + j) * 512 + n * 64 + k;
    __nv_bfloat16 h, l;
    bf16_split(W[idx], h, l);
    g_Wtbh[dst] = h;
    g_Wtbl[dst] = l;
}

// ---------------- HMMA core ----------------
__device__ __forceinline__ void mma16816(float* c, const uint32_t* a, const uint32_t* b) {
    asm volatile(
        "mma.sync.aligned.m16n8k16.row.col.f32.bf16.bf16.f32 "
        "{%0,%1,%2,%3}, {%4,%5,%6,%7}, {%8,%9}, {%0,%1,%2,%3};"
        : "+f"(c[0]), "+f"(c[1]), "+f"(c[2]), "+f"(c[3])
        : "r"(a[0]), "r"(a[1]), "r"(a[2]), "r"(a[3]), "r"(b[0]), "r"(b[1]));
}

static constexpr int LDT = 72;   // padded smem stride (bf16 elems) for K=64 tiles

// ---------------- GEMM1 (HMMA): S1[256x4096] = c[256x512] @ Wtb^T --------------
// tile 64m x 128n, K-loop 8 x 64.  Epilogue writes bf16 hi/lo S1 directly.
static constexpr int G1_A = 64 * LDT;
static constexpr int G1_B = 128 * LDT;
static constexpr int G1_BYTES = (2 * G1_A + 2 * G1_B) * 2;   // 55296

__global__ void __launch_bounds__(256) k_gemm1() {
    extern __shared__ __nv_bfloat16 s1[];
    __nv_bfloat16* Ah = s1;
    __nv_bfloat16* Al = Ah + G1_A;
    __nv_bfloat16* Bh = Al + G1_A;
    __nv_bfloat16* Bl = Bh + G1_B;

    int tid = threadIdx.x;
    int wid = tid >> 5, lane = tid & 31;
    int g = lane >> 2, tg = lane & 3;
    int n0 = blockIdx.x * 128;
    int m0 = blockIdx.y * 64;
    int wm = (wid >> 2) * 32, wn = (wid & 3) * 32;

    float acc[2][4][4] = {};

    for (int k0 = 0; k0 < 512; k0 += 64) {
        for (int t = tid; t < 512; t += 256) {
            int row = t >> 3, cc = t & 7;
            int d = row * LDT + cc * 8;
            size_t s = (size_t)(m0 + row) * 512 + k0 + cc * 8;
            *(uint4*)(Ah + d) = *(const uint4*)(g_Ch + s);
            *(uint4*)(Al + d) = *(const uint4*)(g_Cl + s);
        }
        for (int t = tid; t < 1024; t += 256) {
            int row = t >> 3, cc = t & 7;
            int d = row * LDT + cc * 8;
            size_t s = (size_t)(n0 + row) * 512 + k0 + cc * 8;
            *(uint4*)(Bh + d) = *(const uint4*)(g_Wtbh + s);
            *(uint4*)(Bl + d) = *(const uint4*)(g_Wtbl + s);
        }
        __syncthreads();
#pragma unroll
        for (int ks = 0; ks < 4; ks++) {
            int kc = ks * 16 + tg * 2;
            uint32_t fbh[4][2], fbl[4][2];
#pragma unroll
            for (int nt = 0; nt < 4; nt++) {
                int n = (wn + nt * 8 + g) * LDT + kc;
                fbh[nt][0] = *(const uint32_t*)(Bh + n);
                fbh[nt][1] = *(const uint32_t*)(Bh + n + 8);
                fbl[nt][0] = *(const uint32_t*)(Bl + n);
                fbl[nt][1] = *(const uint32_t*)(Bl + n + 8);
            }
            uint32_t fa[2][4];
#pragma unroll
            for (int mt = 0; mt < 2; mt++) {
                int r0 = (wm + mt * 16 + g) * LDT + kc;
                int r1 = r0 + 8 * LDT;
                fa[mt][0] = *(const uint32_t*)(Ah + r0);
                fa[mt][1] = *(const uint32_t*)(Ah + r1);
                fa[mt][2] = *(const uint32_t*)(Ah + r0 + 8);
                fa[mt][3] = *(const uint32_t*)(Ah + r1 + 8);
            }
#pragma unroll
            for (int mt = 0; mt < 2; mt++)
#pragma unroll
                for (int nt = 0; nt < 4; nt++) {
                    mma16816(acc[mt][nt], fa[mt], fbh[nt]);
                    mma16816(acc[mt][nt], fa[mt], fbl[nt]);
                }
#pragma unroll
            for (int mt = 0; mt < 2; mt++) {
                int r0 = (wm + mt * 16 + g) * LDT + kc;
                int r1 = r0 + 8 * LDT;
                fa[mt][0] = *(const uint32_t*)(Al + r0);
                fa[mt][1] = *(const uint32_t*)(Al + r1);
                fa[mt][2] = *(const uint32_t*)(Al + r0 + 8);
                fa[mt][3] = *(const uint32_t*)(Al + r1 + 8);
            }
#pragma unroll
            for (int mt = 0; mt < 2; mt++)
#pragma unroll
                for (int nt = 0; nt < 4; nt++)
                    mma16816(acc[mt][nt], fa[mt], fbh[nt]);
        }
        __syncthreads();
    }

    // epilogue: split-store S1 (layout [r][ij] == [(r*64+i)][j])
#pragma unroll
    for (int mt = 0; mt < 2; mt++) {
        int row = m0 + wm + mt * 16 + g;
#pragma unroll
        for (int nt = 0; nt < 4; nt++) {
            int col = n0 + wn + nt * 8 + tg * 2;
            __nv_bfloat16 h0, l0, h1, l1;
#pragma unroll
            for (int half = 0; half < 2; half++) {
                int r = row + half * 8;
                bf16_split(acc[mt][nt][half * 2 + 0], h0, l0);
                bf16_split(acc[mt][nt][half * 2 + 1], h1, l1);
                *(uint32_t*)(g_S1h + (size_t)r * 4096 + col) = pack2(h0, h1);
                *(uint32_t*)(g_S1l + (size_t)r * 4096 + col) = pack2(l0, l1);
            }
        }
    }
}

// ---------------- GEMM2 (HMMA, transposed output): B3[q][m] = bsum @ S1^T -----
// one-shot K=64, tile 128q x 128m.  Epilogue writes bf16 hi/lo B3 directly.
static constexpr int TILE_E = 128 * LDT;
static constexpr int SM4_BYTES = 4 * TILE_E * 2;   // 73728

__global__ void __launch_bounds__(256) k_gemm2() {
    extern __shared__ __nv_bfloat16 sm2[];
    __nv_bfloat16* Ah = sm2;
    __nv_bfloat16* Al = Ah + TILE_E;
    __nv_bfloat16* Bh = Al + TILE_E;
    __nv_bfloat16* Bl = Bh + TILE_E;

    int tid = threadIdx.x;
    int wid = tid >> 5, lane = tid & 31;
    int g = lane >> 2, tg = lane & 3;
    int m0 = blockIdx.x * 128;   // m (S1 row / B3 col)
    int q0 = blockIdx.y * 128;   // q

    for (int t = tid; t < 1024; t += 256) {
        int row = t >> 3, cc = t & 7;
        int d = row * LDT + cc * 8;
        size_t sa = (size_t)(q0 + row) * 64 + cc * 8;
        size_t sb = (size_t)(m0 + row) * 64 + cc * 8;
        *(uint4*)(Ah + d) = *(const uint4*)(g_bsumh + sa);
        *(uint4*)(Al + d) = *(const uint4*)(g_bsuml + sa);
        *(uint4*)(Bh + d) = *(const uint4*)(g_S1h + sb);
        *(uint4*)(Bl + d) = *(const uint4*)(g_S1l + sb);
    }
    __syncthreads();

    int wm = (wid >> 2) * 64, wn = (wid & 3) * 32;
    float acc[4][4][4] = {};

#pragma unroll
    for (int ks = 0; ks < 4; ks++) {
        int kc = ks * 16 + tg * 2;
        uint32_t fbh[4][2], fbl[4][2];
#pragma unroll
        for (int nt = 0; nt < 4; nt++) {
            int n = (wn + nt * 8 + g) * LDT + kc;
            fbh[nt][0] = *(const uint32_t*)(Bh + n);
            fbh[nt][1] = *(const uint32_t*)(Bh + n + 8);
            fbl[nt][0] = *(const uint32_t*)(Bl + n);
            fbl[nt][1] = *(const uint32_t*)(Bl + n + 8);
        }
        uint32_t fa[4][4];
#pragma unroll
        for (int mt = 0; mt < 4; mt++) {
            int r0 = (wm + mt * 16 + g) * LDT + kc;
            int r1 = r0 + 8 * LDT;
            fa[mt][0] = *(const uint32_t*)(Ah + r0);
            fa[mt][1] = *(const uint32_t*)(Ah + r1);
            fa[mt][2] = *(const uint32_t*)(Ah + r0 + 8);
            fa[mt][3] = *(const uint32_t*)(Ah + r1 + 8);
        }
#pragma unroll
        for (int mt = 0; mt < 4; mt++)
#pragma unroll
            for (int nt = 0; nt < 4; nt++) {
                mma16816(acc[mt][nt], fa[mt], fbh[nt]);
                mma16816(acc[mt][nt], fa[mt], fbl[nt]);
            }
#pragma unroll
        for (int mt = 0; mt < 4; mt++) {
            int r0 = (wm + mt * 16 + g) * LDT + kc;
            int r1 = r0 + 8 * LDT;
            fa[mt][0] = *(const uint32_t*)(Al + r0);
            fa[mt][1] = *(const uint32_t*)(Al + r1);
            fa[mt][2] = *(const uint32_t*)(Al + r0 + 8);
            fa[mt][3] = *(const uint32_t*)(Al + r1 + 8);
        }
#pragma unroll
        for (int mt = 0; mt < 4; mt++)
#pragma unroll
            for (int nt = 0; nt < 4; nt++)
                mma16816(acc[mt][nt], fa[mt], fbh[nt]);
    }

    // epilogue: B3[q][m] bf16 hi/lo  (offset q*16384+m == (q*256+r)*64+i)
#pragma unroll
    for (int mt = 0; mt < 4; mt++) {
        int qrow = q0 + wm + mt * 16 + g;
#pragma unroll
        for (int nt = 0; nt < 4; nt++) {
            int col = m0 + wn + nt * 8 + tg * 2;
            __nv_bfloat16 h0, l0, h1, l1;
#pragma unroll
            for (int half = 0; half < 2; half++) {
                int q = qrow + half * 8;
                bf16_split(acc[mt][nt][half * 2 + 0], h0, l0);
                bf16_split(acc[mt][nt][half * 2 + 1], h1, l1);
                *(uint32_t*)(g_B3h + (size_t)q * 16384 + col) = pack2(h0, h1);
                *(uint32_t*)(g_B3l + (size_t)q * 16384 + col) = pack2(l0, l1);
            }
        }
    }
}

// ---------------- GEMM3 (HMMA): out[2048x65536] = A2 @ B3^T, K=64 -------------
static constexpr int SM3_BYTES = 4 * TILE_E * 2;   // 73728

__global__ void __launch_bounds__(256) k_gemm3(float* __restrict__ out) {
    extern __shared__ __nv_bfloat16 sm3[];
    __nv_bfloat16* Ah = sm3;
    __nv_bfloat16* Al = Ah + TILE_E;
    __nv_bfloat16* Bh = Al + TILE_E;
    __nv_bfloat16* Bl = Bh + TILE_E;

    int tid = threadIdx.x;
    int wid = tid >> 5, lane = tid & 31;
    int g = lane >> 2, tg = lane & 3;

    int c0 = blockIdx.x * 128;      // column tile (q*256+r)
    size_t m0 = blockIdx.y * 128;   // row tile (n*256+p)

    {
        const uint4* sA_h = (const uint4*)(g_A2h + m0 * 64);
        const uint4* sA_l = (const uint4*)(g_A2l + m0 * 64);
        const uint4* sB_h = (const uint4*)(g_B3h + (size_t)c0 * 64);
        const uint4* sB_l = (const uint4*)(g_B3l + (size_t)c0 * 64);
        for (int t = tid; t < 1024; t += 256) {
            int row = t >> 3, cc = t & 7;
            int d = row * LDT + cc * 8;
            *(uint4*)(Ah + d) = sA_h[t];
            *(uint4*)(Al + d) = sA_l[t];
            *(uint4*)(Bh + d) = sB_h[t];
            *(uint4*)(Bl + d) = sB_l[t];
        }
    }
    __syncthreads();

    int wm = (wid >> 2) * 64;
    int wn = (wid & 3) * 32;
    float acc[4][4][4] = {};

#pragma unroll
    for (int ks = 0; ks < 4; ks++) {
        int kc = ks * 16 + tg * 2;
        uint32_t fbh[4][2], fbl[4][2];
#pragma unroll
        for (int nt = 0; nt < 4; nt++) {
            int n = (wn + nt * 8 + g) * LDT + kc;
            fbh[nt][0] = *(const uint32_t*)(Bh + n);
            fbh[nt][1] = *(const uint32_t*)(Bh + n + 8);
            fbl[nt][0] = *(const uint32_t*)(Bl + n);
            fbl[nt][1] = *(const uint32_t*)(Bl + n + 8);
        }
        uint32_t fa[4][4];
#pragma unroll
        for (int mt = 0; mt < 4; mt++) {
            int r0 = (wm + mt * 16 + g) * LDT + kc;
            int r1 = r0 + 8 * LDT;
            fa[mt][0] = *(const uint32_t*)(Ah + r0);
            fa[mt][1] = *(const uint32_t*)(Ah + r1);
            fa[mt][2] = *(const uint32_t*)(Ah + r0 + 8);
            fa[mt][3] = *(const uint32_t*)(Ah + r1 + 8);
        }
#pragma unroll
        for (int mt = 0; mt < 4; mt++)
#pragma unroll
            for (int nt = 0; nt < 4; nt++) {
                mma16816(acc[mt][nt], fa[mt], fbh[nt]);
                mma16816(acc[mt][nt], fa[mt], fbl[nt]);
            }
#pragma unroll
        for (int mt = 0; mt < 4; mt++) {
            int r0 = (wm + mt * 16 + g) * LDT + kc;
            int r1 = r0 + 8 * LDT;
            fa[mt][0] = *(const uint32_t*)(Al + r0);
            fa[mt][1] = *(const uint32_t*)(Al + r1);
            fa[mt][2] = *(const uint32_t*)(Al + r0 + 8);
            fa[mt][3] = *(const uint32_t*)(Al + r1 + 8);
        }
#pragma unroll
        for (int mt = 0; mt < 4; mt++)
#pragma unroll
            for (int nt = 0; nt < 4; nt++)
                mma16816(acc[mt][nt], fa[mt], fbh[nt]);
    }

#pragma unroll
    for (int mt = 0; mt < 4; mt++) {
        size_t row = m0 + wm + mt * 16 + g;
        float* o0 = out + row * 65536;
        float* o1 = o0 + 8 * 65536;
#pragma unroll
        for (int nt = 0; nt < 4; nt++) {
            int col = c0 + wn + nt * 8 + tg * 2;
            *(float2*)(o0 + col) = make_float2(acc[mt][nt][0], acc[mt][nt][1]);
            *(float2*)(o1 + col) = make_float2(acc[mt][nt][2], acc[mt][nt][3]);
        }
    }
}

// ---------------- launch ----------------
extern "C" void kernel_launch(void* const* d_in, const int* in_sizes, int n_in,
                              void* d_out, int out_size) {
    const float* c = (const float*)d_in[0];   // [1,256,8,64]
    const float* b = (const float*)d_in[1];   // [1,256,8,64]
    const float* a = (const float*)d_in[2];   // [1,256,8,64]
    const float* W = (const float*)d_in[3];   // [8,64,64,64]
    float* out = (float*)d_out;               // [1,8,256,256,256]

    cudaFuncSetAttribute(k_gemm1, cudaFuncAttributeMaxDynamicSharedMemorySize, G1_BYTES);
    cudaFuncSetAttribute(k_gemm2, cudaFuncAttributeMaxDynamicSharedMemorySize, SM4_BYTES);
    cudaFuncSetAttribute(k_gemm3, cudaFuncAttributeMaxDynamicSharedMemorySize, SM3_BYTES);

    k_bsum<<<64, 256>>>(b);
    k_csplit<<<512, 256>>>(c);
    k_a2<<<512, 256>>>(a);
    k_wt<<<8192, 256>>>(W);
    k_gemm1<<<dim3(32, 4), 256, G1_BYTES>>>();
    k_gemm2<<<dim3(128, 2), 256, SM4_BYTES>>>();
    k_gemm3<<<dim3(512, 16), 256, SM3_BYTES>>>(out);
}